// round 4
// baseline (speedup 1.0000x reference)
#include <cuda_runtime.h>
#include <math.h>

#define BB  32
#define PP  24
#define HHN 24
#define EE  300
#define DD  512
#define GG  4096   // 8*D
#define HP  25     // H+1 (padded grid dim)

// Grid state with zero-padding at row 0 / col 0 (never written -> stays zero).
// Cell (i,j) stored at [(i+1)*HP + (j+1)].
__device__ float g_h[(PP+1)*HP][BB][DD];
__device__ float g_c[(PP+1)*HP][BB][DD];
// Hoisted input projections: A[i] = prem_emb[i] @ W_ih[:, :E].T + b_ih + b_hh
//                            Bh[j] = hyp_emb[j] @ W_ih[:, E:].T
__device__ float g_A[PP][BB][GG];
__device__ float g_Bh[HHN][BB][GG];
// Per-diagonal LSTM cell outputs (pre-condense), indexed by cell-on-diagonal.
__device__ float g_h2[HHN][BB][2*DD];
__device__ float g_c2[HHN][BB][2*DD];
// MLP intermediates
__device__ float g_m1[BB][DD];
__device__ float g_m2[BB][DD];

__device__ __forceinline__ float sigf(float x) { return 1.0f / (1.0f + expf(-x)); }

// ---------------------------------------------------------------------------
// Prologue: gather embeddings + input GEMMs into g_A / g_Bh.
// grid = (24 seq, 32 n-chunks of 128, 2 [A|Bh]), block = 256
// C[32 x 128], K = 300 (padded to 320)
// ---------------------------------------------------------------------------
__global__ void __launch_bounds__(256) prologue_kernel(
    const int* __restrict__ premise, const int* __restrict__ hypothesis,
    const float* __restrict__ emb, const float* __restrict__ W_ih,
    const float* __restrict__ b_ih, const float* __restrict__ b_hh)
{
    int seq = blockIdx.x;
    int n0  = blockIdx.y * 128;
    bool isA = (blockIdx.z == 0);
    const int* sidx = isA ? premise : hypothesis;   // both [B,24] row-major
    int coff = isA ? 0 : EE;

    __shared__ float Xs[32][33];
    __shared__ float Ws[128][33];
    __shared__ int   rows[32];

    int tid = threadIdx.x;
    int tr = tid >> 5, tc = tid & 31;
    if (tid < 32) rows[tid] = sidx[tid * 24 + seq];
    __syncthreads();

    float acc[4][4];
#pragma unroll
    for (int a = 0; a < 4; a++)
#pragma unroll
        for (int b = 0; b < 4; b++) acc[a][b] = 0.f;

    for (int k0 = 0; k0 < 320; k0 += 32) {
        {
            int b = tid >> 3;
            int kq = (tid & 7) * 4;
            int k = k0 + kq;
            float4 v = make_float4(0.f, 0.f, 0.f, 0.f);
            if (k < EE) v = *(const float4*)(emb + (long)rows[b] * EE + k);
            Xs[b][kq] = v.x; Xs[b][kq + 1] = v.y; Xs[b][kq + 2] = v.z; Xs[b][kq + 3] = v.w;
        }
#pragma unroll
        for (int t = 0; t < 4; t++) {
            int idx = tid + t * 256;
            int n = idx >> 3;
            int kq = (idx & 7) * 4;
            int k = k0 + kq;
            float4 w = make_float4(0.f, 0.f, 0.f, 0.f);
            if (k < EE) w = *(const float4*)(W_ih + (long)(n0 + n) * (2 * EE) + coff + k);
            Ws[n][kq] = w.x; Ws[n][kq + 1] = w.y; Ws[n][kq + 2] = w.z; Ws[n][kq + 3] = w.w;
        }
        __syncthreads();
#pragma unroll
        for (int kk = 0; kk < 32; kk++) {
            float xv[4], wv[4];
#pragma unroll
            for (int rr = 0; rr < 4; rr++) xv[rr] = Xs[tr + 8 * rr][kk];
#pragma unroll
            for (int cc = 0; cc < 4; cc++) wv[cc] = Ws[cc * 32 + tc][kk];
#pragma unroll
            for (int rr = 0; rr < 4; rr++)
#pragma unroll
                for (int cc = 0; cc < 4; cc++)
                    acc[rr][cc] = fmaf(xv[rr], wv[cc], acc[rr][cc]);
        }
        __syncthreads();
    }

    float* dst = isA ? &g_A[seq][0][0] : &g_Bh[seq][0][0];
#pragma unroll
    for (int rr = 0; rr < 4; rr++) {
        int b = tr + 8 * rr;
#pragma unroll
        for (int cc = 0; cc < 4; cc++) {
            int n = n0 + cc * 32 + tc;
            float v = acc[rr][cc];
            if (isA) v += b_ih[n] + b_hh[n];
            dst[b * GG + n] = v;
        }
    }
}

// ---------------------------------------------------------------------------
// Gates kernel (per diagonal): recurrent GEMM + fused LSTM nonlinearity.
// grid = (ncells, 16 m-chunks of 64), block = 256
// Block computes, for its cell, gate pre-activations for 4 gates x 64 m-cols:
//   C[32 x 256], K = 1024 (hcat = [left_h | lower_h]); 32 outputs/thread.
// Then applies i/f/g/o nonlinearity and writes h2, c2 chunks.
// ---------------------------------------------------------------------------
__global__ void __launch_bounds__(256) gates_kernel(
    const float* __restrict__ W_hh, int d, int i_lo)
{
    int ci = blockIdx.x;
    int i = i_lo + ci;
    int j = d - i;
    int m0 = blockIdx.y * 64;

    const float* leftH = &g_h[i * HP + (j + 1)][0][0];       // cell (i-1, j)
    const float* lowH  = &g_h[(i + 1) * HP + j][0][0];       // cell (i, j-1)
    const float* leftC = &g_c[i * HP + (j + 1)][0][0];
    const float* lowC  = &g_c[(i + 1) * HP + j][0][0];

    __shared__ float Xs[32][33];
    __shared__ float Ws[256][33];

    int tid = threadIdx.x;
    int tr = tid >> 5, tc = tid & 31;

    float acc[4][8];
#pragma unroll
    for (int a = 0; a < 4; a++)
#pragma unroll
        for (int b = 0; b < 8; b++) acc[a][b] = 0.f;

    for (int k0 = 0; k0 < 1024; k0 += 32) {
        {
            int b = tid >> 3;
            int kq = (tid & 7) * 4;
            int k = k0 + kq;
            const float* src = (k < DD) ? (leftH + b * DD + k) : (lowH + b * DD + (k - DD));
            float4 v = *(const float4*)src;
            Xs[b][kq] = v.x; Xs[b][kq + 1] = v.y; Xs[b][kq + 2] = v.z; Xs[b][kq + 3] = v.w;
        }
#pragma unroll
        for (int t = 0; t < 8; t++) {
            int idx = tid + t * 256;          // 0..2047 float4 slots
            int n = idx >> 3;                 // local col 0..255
            int kq = (idx & 7) * 4;
            int grow = ((n >> 6) << 10) + m0 + (n & 63);   // gate*1024 + m
            float4 w = *(const float4*)(W_hh + (long)grow * 1024 + k0 + kq);
            Ws[n][kq] = w.x; Ws[n][kq + 1] = w.y; Ws[n][kq + 2] = w.z; Ws[n][kq + 3] = w.w;
        }
        __syncthreads();
#pragma unroll
        for (int kk = 0; kk < 32; kk++) {
            float xv[4], wv[8];
#pragma unroll
            for (int rr = 0; rr < 4; rr++) xv[rr] = Xs[tr + 8 * rr][kk];
#pragma unroll
            for (int cc = 0; cc < 8; cc++) wv[cc] = Ws[cc * 32 + tc][kk];
#pragma unroll
            for (int rr = 0; rr < 4; rr++)
#pragma unroll
                for (int cc = 0; cc < 8; cc++)
                    acc[rr][cc] = fmaf(xv[rr], wv[cc], acc[rr][cc]);
        }
        __syncthreads();
    }

    // Elementwise LSTM. Thread's cols: local n = cc*32+tc -> gate = cc>>1, mi = cc&1,
    // m = m0 + mi*32 + tc. Each thread holds all 4 gates for its (b, m) pairs.
    const float* Ai = &g_A[i][0][0];
    const float* Bj = &g_Bh[j][0][0];
    float* h2o = &g_h2[ci][0][0];
    float* c2o = &g_c2[ci][0][0];
#pragma unroll
    for (int rr = 0; rr < 4; rr++) {
        int b = tr + 8 * rr;
#pragma unroll
        for (int mi = 0; mi < 2; mi++) {
            int m = m0 + mi * 32 + tc;
            float gi = acc[rr][0 + mi] + Ai[b * GG + m]        + Bj[b * GG + m];
            float gf = acc[rr][2 + mi] + Ai[b * GG + 1024 + m] + Bj[b * GG + 1024 + m];
            float gg = acc[rr][4 + mi] + Ai[b * GG + 2048 + m] + Bj[b * GG + 2048 + m];
            float go = acc[rr][6 + mi] + Ai[b * GG + 3072 + m] + Bj[b * GG + 3072 + m];
            float cp = (m < DD) ? leftC[b * DD + m] : lowC[b * DD + m - DD];
            float c2 = sigf(gf) * cp + sigf(gi) * tanhf(gg);
            float h2 = sigf(go) * tanhf(c2);
            c2o[b * (2 * DD) + m] = c2;
            h2o[b * (2 * DD) + m] = h2;
        }
    }
}

// ---------------------------------------------------------------------------
// Condense kernel (per diagonal): nh = h2 @ W_ch.T + b_ch ; nc = c2 @ W_cc.T + b_cc
// grid = (ncells, 8) : y>>2 selects h/c, y&3 selects 128-col chunk of 512.
// C[32 x 128], K = 1024. Writes into padded grid at (i+1, j+1).
// ---------------------------------------------------------------------------
__global__ void __launch_bounds__(256) condense_kernel(
    const float* __restrict__ W_ch, const float* __restrict__ b_ch,
    const float* __restrict__ W_cc, const float* __restrict__ b_cc,
    int d, int i_lo)
{
    int ci = blockIdx.x;
    int i = i_lo + ci;
    int j = d - i;
    int which = blockIdx.y >> 2;            // 0 -> h path, 1 -> c path
    int n0 = (blockIdx.y & 3) * 128;

    const float* X    = which ? &g_c2[ci][0][0] : &g_h2[ci][0][0];
    const float* W    = which ? W_cc : W_ch;
    const float* bias = which ? b_cc : b_ch;
    float* out = which ? &g_c[(i + 1) * HP + (j + 1)][0][0]
                       : &g_h[(i + 1) * HP + (j + 1)][0][0];

    __shared__ float Xs[32][33];
    __shared__ float Ws[128][33];
    int tid = threadIdx.x;
    int tr = tid >> 5, tc = tid & 31;

    float acc[4][4];
#pragma unroll
    for (int a = 0; a < 4; a++)
#pragma unroll
        for (int b = 0; b < 4; b++) acc[a][b] = 0.f;

    for (int k0 = 0; k0 < 1024; k0 += 32) {
        {
            int b = tid >> 3;
            int kq = (tid & 7) * 4;
            float4 v = *(const float4*)(X + b * (2 * DD) + k0 + kq);
            Xs[b][kq] = v.x; Xs[b][kq + 1] = v.y; Xs[b][kq + 2] = v.z; Xs[b][kq + 3] = v.w;
        }
#pragma unroll
        for (int t = 0; t < 4; t++) {
            int idx = tid + t * 256;
            int n = idx >> 3;
            int kq = (idx & 7) * 4;
            float4 w = *(const float4*)(W + (long)(n0 + n) * 1024 + k0 + kq);
            Ws[n][kq] = w.x; Ws[n][kq + 1] = w.y; Ws[n][kq + 2] = w.z; Ws[n][kq + 3] = w.w;
        }
        __syncthreads();
#pragma unroll
        for (int kk = 0; kk < 32; kk++) {
            float xv[4], wv[4];
#pragma unroll
            for (int rr = 0; rr < 4; rr++) xv[rr] = Xs[tr + 8 * rr][kk];
#pragma unroll
            for (int cc = 0; cc < 4; cc++) wv[cc] = Ws[cc * 32 + tc][kk];
#pragma unroll
            for (int rr = 0; rr < 4; rr++)
#pragma unroll
                for (int cc = 0; cc < 4; cc++)
                    acc[rr][cc] = fmaf(xv[rr], wv[cc], acc[rr][cc]);
        }
        __syncthreads();
    }

#pragma unroll
    for (int rr = 0; rr < 4; rr++) {
        int b = tr + 8 * rr;
#pragma unroll
        for (int cc = 0; cc < 4; cc++) {
            int n = n0 + cc * 32 + tc;
            out[b * DD + n] = acc[rr][cc] + bias[n];
        }
    }
}

// ---------------------------------------------------------------------------
// MLP layer: out = relu(X @ W.T + b), C[32 x 512], K = 512. grid = 4 blocks.
// stage 0: X = final grid cell h, out = g_m1 ; stage 1: X = g_m1, out = g_m2
// ---------------------------------------------------------------------------
__global__ void __launch_bounds__(256) mlp_kernel(
    const float* __restrict__ W, const float* __restrict__ bias, int stage)
{
    const float* X = (stage == 0) ? &g_h[PP * HP + HHN][0][0] : &g_m1[0][0];
    float* out = (stage == 0) ? &g_m1[0][0] : &g_m2[0][0];
    int n0 = blockIdx.x * 128;

    __shared__ float Xs[32][33];
    __shared__ float Ws[128][33];
    int tid = threadIdx.x;
    int tr = tid >> 5, tc = tid & 31;

    float acc[4][4];
#pragma unroll
    for (int a = 0; a < 4; a++)
#pragma unroll
        for (int b = 0; b < 4; b++) acc[a][b] = 0.f;

    for (int k0 = 0; k0 < DD; k0 += 32) {
        {
            int b = tid >> 3;
            int kq = (tid & 7) * 4;
            float4 v = *(const float4*)(X + b * DD + k0 + kq);
            Xs[b][kq] = v.x; Xs[b][kq + 1] = v.y; Xs[b][kq + 2] = v.z; Xs[b][kq + 3] = v.w;
        }
#pragma unroll
        for (int t = 0; t < 4; t++) {
            int idx = tid + t * 256;
            int n = idx >> 3;
            int kq = (idx & 7) * 4;
            float4 w = *(const float4*)(W + (long)(n0 + n) * DD + k0 + kq);
            Ws[n][kq] = w.x; Ws[n][kq + 1] = w.y; Ws[n][kq + 2] = w.z; Ws[n][kq + 3] = w.w;
        }
        __syncthreads();
#pragma unroll
        for (int kk = 0; kk < 32; kk++) {
            float xv[4], wv[4];
#pragma unroll
            for (int rr = 0; rr < 4; rr++) xv[rr] = Xs[tr + 8 * rr][kk];
#pragma unroll
            for (int cc = 0; cc < 4; cc++) wv[cc] = Ws[cc * 32 + tc][kk];
#pragma unroll
            for (int rr = 0; rr < 4; rr++)
#pragma unroll
                for (int cc = 0; cc < 4; cc++)
                    acc[rr][cc] = fmaf(xv[rr], wv[cc], acc[rr][cc]);
        }
        __syncthreads();
    }

#pragma unroll
    for (int rr = 0; rr < 4; rr++) {
        int b = tr + 8 * rr;
#pragma unroll
        for (int cc = 0; cc < 4; cc++) {
            int n = n0 + cc * 32 + tc;
            out[b * DD + n] = fmaxf(acc[rr][cc] + bias[n], 0.f);
        }
    }
}

// ---------------------------------------------------------------------------
// Final: logits = g_m2 @ W3.T + b3 ; softmax over 3 classes. out [32,3] f32.
// ---------------------------------------------------------------------------
__global__ void __launch_bounds__(128) final_kernel(
    const float* __restrict__ W3, const float* __restrict__ b3, float* __restrict__ out)
{
    __shared__ float logits[32][3];
    int t = threadIdx.x;
    if (t < 96) {
        int b = t / 3, c = t % 3;
        float s = b3[c];
        for (int k = 0; k < DD; k++) s += g_m2[b][k] * W3[c * DD + k];
        logits[b][c] = s;
    }
    __syncthreads();
    if (t < 96) {
        int b = t / 3, c = t % 3;
        float mx = fmaxf(logits[b][0], fmaxf(logits[b][1], logits[b][2]));
        float e0 = expf(logits[b][0] - mx);
        float e1 = expf(logits[b][1] - mx);
        float e2 = expf(logits[b][2] - mx);
        out[b * 3 + c] = expf(logits[b][c] - mx) / (e0 + e1 + e2);
    }
}

// ---------------------------------------------------------------------------
extern "C" void kernel_launch(void* const* d_in, const int* in_sizes, int n_in,
                              void* d_out, int out_size)
{
    const int*   premise    = (const int*)d_in[0];
    const int*   hypothesis = (const int*)d_in[1];
    const float* emb        = (const float*)d_in[2];
    const float* W_ih       = (const float*)d_in[3];
    const float* W_hh       = (const float*)d_in[4];
    const float* b_ih       = (const float*)d_in[5];
    const float* b_hh       = (const float*)d_in[6];
    const float* W_ch       = (const float*)d_in[7];
    const float* b_ch       = (const float*)d_in[8];
    const float* W_cc       = (const float*)d_in[9];
    const float* b_cc       = (const float*)d_in[10];
    const float* W1         = (const float*)d_in[11];
    const float* b1         = (const float*)d_in[12];
    const float* W2         = (const float*)d_in[13];
    const float* b2         = (const float*)d_in[14];
    const float* W3         = (const float*)d_in[15];
    const float* b3         = (const float*)d_in[16];
    float* out = (float*)d_out;

    prologue_kernel<<<dim3(24, 32, 2), 256>>>(premise, hypothesis, emb, W_ih, b_ih, b_hh);

    for (int d = 0; d <= PP + HHN - 2; d++) {
        int i_lo = d - (HHN - 1); if (i_lo < 0) i_lo = 0;
        int i_hi = d < (PP - 1) ? d : (PP - 1);
        int nc = i_hi - i_lo + 1;
        gates_kernel<<<dim3(nc, 16), 256>>>(W_hh, d, i_lo);
        condense_kernel<<<dim3(nc, 8), 256>>>(W_ch, b_ch, W_cc, b_cc, d, i_lo);
    }

    mlp_kernel<<<4, 256>>>(W1, b1, 0);
    mlp_kernel<<<4, 256>>>(W2, b2, 1);
    final_kernel<<<1, 128>>>(W3, b3, out);
}